// round 2
// baseline (speedup 1.0000x reference)
#include <cuda_runtime.h>
#include <math.h>

// Problem constants
#define Bv     4
#define Nv     8192
#define Sv     2048
#define LOWD   512
#define SKIPD  256
#define OUTD   256
#define IND    768          // SKIPD + LOWD

// Scratch (device globals; no allocation allowed)
__device__ float g_w[(size_t)Bv * Nv * 3];      // IDW weights
__device__ int   g_idx[(size_t)Bv * Nv * 3];    // KNN indices

// TF32 input rounding (what TF32 tensor cores / cublas-TF32 do to operands)
__device__ __forceinline__ float tf32r(float x) {
    asm("cvt.rna.tf32.f32 %0, %1;" : "=f"(x) : "f"(x));
    return x;
}

// ---------------------------------------------------------------------------
// Kernel 1: brute-force 3-NN + IDW weights.
// One block = 256 query points of one batch. xyz_lo staged in SMEM (SoA).
// Arithmetic mirrors the reference: d2 = (|q|^2 + |p|^2) - 2*(q.p),
// dot accumulated in ascending coordinate order with fma.
// ---------------------------------------------------------------------------
__global__ __launch_bounds__(256) void knn_kernel(const float* __restrict__ xyz_hi,
                                                  const float* __restrict__ xyz_lo) {
    __shared__ float px[Sv], py[Sv], pz[Sv], pp[Sv];   // 32 KB
    const int b     = blockIdx.x >> 5;                 // 32 blocks / batch
    const int qbase = (blockIdx.x & 31) * 256;
    const int tid   = threadIdx.x;

    for (int s = tid; s < Sv; s += 256) {
        float x = xyz_lo[((size_t)b * Sv + s) * 3 + 0];
        float y = xyz_lo[((size_t)b * Sv + s) * 3 + 1];
        float z = xyz_lo[((size_t)b * Sv + s) * 3 + 2];
        px[s] = x; py[s] = y; pz[s] = z;
        pp[s] = fmaf(z, z, fmaf(y, y, x * x));
    }
    __syncthreads();

    const int q = b * Nv + qbase + tid;
    const float qx = xyz_hi[(size_t)q * 3 + 0];
    const float qy = xyz_hi[(size_t)q * 3 + 1];
    const float qz = xyz_hi[(size_t)q * 3 + 2];
    const float qq = fmaf(qz, qz, fmaf(qy, qy, qx * qx));

    float d0 = 1e30f, d1 = 1e30f, d2 = 1e30f;
    int   i0 = 0,     i1 = 0,     i2 = 0;

    for (int s = 0; s < Sv; s++) {
        float dot = fmaf(qz, pz[s], fmaf(qy, py[s], qx * px[s]));
        float d   = __fsub_rn(__fadd_rn(qq, pp[s]), __fmul_rn(2.0f, dot));
        if (d < d2) {
            if (d < d1) {
                d2 = d1; i2 = i1;
                if (d < d0) { d1 = d0; i1 = i0; d0 = d; i0 = s; }
                else        { d1 = d;  i1 = s; }
            } else { d2 = d; i2 = s; }
        }
    }

    float r0 = 1.0f / (sqrtf(fmaxf(d0, 0.0f)) + 1e-8f);
    float r1 = 1.0f / (sqrtf(fmaxf(d1, 0.0f)) + 1e-8f);
    float r2 = 1.0f / (sqrtf(fmaxf(d2, 0.0f)) + 1e-8f);
    float inv = 1.0f / (r0 + r1 + r2);
    g_w[(size_t)q * 3 + 0] = r0 * inv;
    g_w[(size_t)q * 3 + 1] = r1 * inv;
    g_w[(size_t)q * 3 + 2] = r2 * inv;
    g_idx[(size_t)q * 3 + 0] = i0;
    g_idx[(size_t)q * 3 + 1] = i1;
    g_idx[(size_t)q * 3 + 2] = i2;
}

// ---------------------------------------------------------------------------
// Kernel 2 (fused): exact reference dataflow with TF32-emulated GEMMs.
//   A-tile cols   0..255: feat_skip
//   A-tile cols 256..767: interp = w0*f[i0] + w1*f[i1] + w2*f[i2] (on the fly)
//   h  = relu(A @ tf32(W1) + b1)        (A rounded to tf32 at SMEM store)
//   h2 = tf32(h) @ tf32(W2) + b2
//   out = LayerNorm(h2)*gamma + beta    (two-pass, fp32)
// 64-row tiles (512 blocks), 256 threads, 4x16 microtile/thread, BK = 32.
// ---------------------------------------------------------------------------
__global__ __launch_bounds__(256) void fused_mlp_kernel(
        const float* __restrict__ feat_skip,
        const float* __restrict__ feat_lo,
        const float* __restrict__ W1,
        const float* __restrict__ b1,
        const float* __restrict__ W2,
        const float* __restrict__ b2,
        const float* __restrict__ gamma,
        const float* __restrict__ beta,
        float* __restrict__ out) {
    extern __shared__ float smem[];
    float* As  = smem;                        // [32][64]   2048 floats
    float* Bs  = smem + 2048;                 // [32][256]  8192 floats
    float* Hs  = smem + 2048 + 8192;          // [64][256] 16384 floats
    float* Wsm = smem + 2048 + 8192 + 16384;  // [64*3]      192 floats
    int*   Ism = (int*)(Wsm + 192);           // [64*3]      192 ints

    const int m0  = blockIdx.x * 64;     // global row in B*N
    const int b   = m0 >> 13;            // / Nv
    const int tid = threadIdx.x;
    const int tx  = tid & 15, ty = tid >> 4;

    if (tid < 192) {
        Wsm[tid] = g_w[(size_t)m0 * 3 + tid];
        Ism[tid] = g_idx[(size_t)m0 * 3 + tid];
    }
    __syncthreads();

    float acc[4][16];
#pragma unroll
    for (int r = 0; r < 4; r++)
#pragma unroll
        for (int j = 0; j < 16; j++) acc[r][j] = 0.0f;

    // ---- GEMM 1: [64 x 768] @ W1[768 x 256] ----
    for (int k0 = 0; k0 < IND; k0 += 32) {
        // A tile: 64 rows x 32 cols, stored transposed As[k][m], tf32-rounded
#pragma unroll
        for (int i = 0; i < 2; i++) {
            int lin = tid + i * 256;           // 0..511 float4 jobs
            int row = lin >> 3;
            int kc  = (lin & 7) * 4;
            float4 v;
            if (k0 < SKIPD) {
                v = *(const float4*)(feat_skip + (size_t)(m0 + row) * SKIPD + k0 + kc);
            } else {
                const int kb = k0 - SKIPD + kc;
                const float w0 = Wsm[row * 3 + 0];
                const float w1 = Wsm[row * 3 + 1];
                const float w2 = Wsm[row * 3 + 2];
                const float* f0 = feat_lo + ((size_t)b * Sv + Ism[row * 3 + 0]) * LOWD + kb;
                const float* f1 = feat_lo + ((size_t)b * Sv + Ism[row * 3 + 1]) * LOWD + kb;
                const float* f2 = feat_lo + ((size_t)b * Sv + Ism[row * 3 + 2]) * LOWD + kb;
                float4 c0 = *(const float4*)f0;
                float4 c1 = *(const float4*)f1;
                float4 c2 = *(const float4*)f2;
                v.x = fmaf(w2, c2.x, fmaf(w1, c1.x, w0 * c0.x));
                v.y = fmaf(w2, c2.y, fmaf(w1, c1.y, w0 * c0.y));
                v.z = fmaf(w2, c2.z, fmaf(w1, c1.z, w0 * c0.z));
                v.w = fmaf(w2, c2.w, fmaf(w1, c1.w, w0 * c0.w));
            }
            As[(kc + 0) * 64 + row] = tf32r(v.x);
            As[(kc + 1) * 64 + row] = tf32r(v.y);
            As[(kc + 2) * 64 + row] = tf32r(v.z);
            As[(kc + 3) * 64 + row] = tf32r(v.w);
        }
        // B tile: W1 rows k0..k0+31, tf32-rounded
#pragma unroll
        for (int i = 0; i < 8; i++) {
            int lin = tid + i * 256;
            int r = lin >> 6;
            int c = (lin & 63) * 4;
            float4 v = *(const float4*)(W1 + (size_t)(k0 + r) * OUTD + c);
            Bs[r * 256 + c + 0] = tf32r(v.x);
            Bs[r * 256 + c + 1] = tf32r(v.y);
            Bs[r * 256 + c + 2] = tf32r(v.z);
            Bs[r * 256 + c + 3] = tf32r(v.w);
        }
        __syncthreads();
#pragma unroll
        for (int kk = 0; kk < 32; kk++) {
            float a[4];
            *(float4*)a = *(const float4*)&As[kk * 64 + ty * 4];
            float bf[16];
#pragma unroll
            for (int j = 0; j < 16; j++) bf[j] = Bs[kk * 256 + tx + 16 * j];
#pragma unroll
            for (int r = 0; r < 4; r++)
#pragma unroll
                for (int j = 0; j < 16; j++)
                    acc[r][j] = fmaf(a[r], bf[j], acc[r][j]);
        }
        __syncthreads();
    }

    // ---- Epilogue 1: + b1, ReLU, tf32-round into SMEM ----
    {
        float bias[16];
#pragma unroll
        for (int j = 0; j < 16; j++) bias[j] = b1[tx + 16 * j];
#pragma unroll
        for (int r = 0; r < 4; r++)
#pragma unroll
            for (int j = 0; j < 16; j++) {
                float v = fmaxf(acc[r][j] + bias[j], 0.0f);
                Hs[(ty * 4 + r) * 256 + tx + 16 * j] = tf32r(v);
            }
    }
    __syncthreads();

    // ---- GEMM 2: h[64 x 256] @ W2[256 x 256] ----
#pragma unroll
    for (int r = 0; r < 4; r++)
#pragma unroll
        for (int j = 0; j < 16; j++) acc[r][j] = 0.0f;

    for (int k0 = 0; k0 < OUTD; k0 += 32) {
#pragma unroll
        for (int i = 0; i < 8; i++) {
            int lin = tid + i * 256;
            int r = lin >> 6;
            int c = (lin & 63) * 4;
            float4 v = *(const float4*)(W2 + (size_t)(k0 + r) * OUTD + c);
            Bs[r * 256 + c + 0] = tf32r(v.x);
            Bs[r * 256 + c + 1] = tf32r(v.y);
            Bs[r * 256 + c + 2] = tf32r(v.z);
            Bs[r * 256 + c + 3] = tf32r(v.w);
        }
        __syncthreads();
#pragma unroll
        for (int kk = 0; kk < 32; kk++) {
            float a[4];
#pragma unroll
            for (int r = 0; r < 4; r++) a[r] = Hs[(ty * 4 + r) * 256 + k0 + kk];
            float bf[16];
#pragma unroll
            for (int j = 0; j < 16; j++) bf[j] = Bs[kk * 256 + tx + 16 * j];
#pragma unroll
            for (int r = 0; r < 4; r++)
#pragma unroll
                for (int j = 0; j < 16; j++)
                    acc[r][j] = fmaf(a[r], bf[j], acc[r][j]);
        }
        __syncthreads();
    }

    // ---- Epilogue 2: + b2, two-pass LayerNorm, write ----
    {
        float bias[16], gm[16], bt[16];
#pragma unroll
        for (int j = 0; j < 16; j++) {
            int n = tx + 16 * j;
            bias[j] = b2[n]; gm[j] = gamma[n]; bt[j] = beta[n];
        }
#pragma unroll
        for (int r = 0; r < 4; r++) {
            float v[16];
            float s = 0.0f;
#pragma unroll
            for (int j = 0; j < 16; j++) {
                v[j] = acc[r][j] + bias[j];
                s += v[j];
            }
#pragma unroll
            for (int off = 8; off >= 1; off >>= 1)
                s += __shfl_xor_sync(0xffffffffu, s, off);
            const float mu = s * (1.0f / 256.0f);

            float sq = 0.0f;
#pragma unroll
            for (int j = 0; j < 16; j++) {
                float d = v[j] - mu;
                sq = fmaf(d, d, sq);
            }
#pragma unroll
            for (int off = 8; off >= 1; off >>= 1)
                sq += __shfl_xor_sync(0xffffffffu, sq, off);
            const float var  = sq * (1.0f / 256.0f);
            const float rstd = rsqrtf(var + 1e-5f);

            float* dst = out + (size_t)(m0 + ty * 4 + r) * OUTD;
#pragma unroll
            for (int j = 0; j < 16; j++)
                dst[tx + 16 * j] = fmaf((v[j] - mu) * rstd, gm[j], bt[j]);
        }
    }
}

// ---------------------------------------------------------------------------
extern "C" void kernel_launch(void* const* d_in, const int* in_sizes, int n_in,
                              void* d_out, int out_size) {
    const float* xyz_hi    = (const float*)d_in[0];
    const float* xyz_lo    = (const float*)d_in[1];
    const float* feat_skip = (const float*)d_in[2];
    const float* feat_lo   = (const float*)d_in[3];
    const float* W1        = (const float*)d_in[4];
    const float* b1        = (const float*)d_in[5];
    const float* W2        = (const float*)d_in[6];
    const float* b2        = (const float*)d_in[7];
    const float* gamma     = (const float*)d_in[8];
    const float* beta      = (const float*)d_in[9];
    float* out = (float*)d_out;

    knn_kernel<<<Bv * (Nv / 256), 256>>>(xyz_hi, xyz_lo);

    const size_t SMEM_FUSED =
        (size_t)(2048 + 8192 + 16384 + 192) * sizeof(float) + 192 * sizeof(int);
    cudaFuncSetAttribute(fused_mlp_kernel,
                         cudaFuncAttributeMaxDynamicSharedMemorySize,
                         (int)SMEM_FUSED);
    fused_mlp_kernel<<<(Bv * Nv) / 64, 256, SMEM_FUSED>>>(
        feat_skip, feat_lo, W1, b1, W2, b2, gamma, beta, out);
}

// round 4
// speedup vs baseline: 3.6000x; 3.6000x over previous
#include <cuda_runtime.h>
#include <cuda_fp16.h>
#include <math.h>
#include <stdint.h>

// Problem constants
#define Bv     4
#define Nv     8192
#define Sv     2048
#define LOWD   512
#define SKIPD  256
#define OUTD   256
#define IND    768

// Scratch (device globals; no allocation allowed)
__device__ float  g_w[(size_t)Bv * Nv * 3];
__device__ int    g_idx[(size_t)Bv * Nv * 3];
__device__ __half g_W1h[(size_t)OUTD * IND];   // W1^T fp16 [n][k]
__device__ __half g_W2h[(size_t)OUTD * OUTD];  // W2^T fp16 [n][k]

// ---------------------------------------------------------------------------
// Helpers (family-portable: ldmatrix / mma.sync / cp.async only)
// ---------------------------------------------------------------------------
__device__ __forceinline__ uint32_t smem_u32(const void* p) {
    uint32_t a;
    asm("{ .reg .u64 t; cvta.to.shared.u64 t, %1; cvt.u32.u64 %0, t; }"
        : "=r"(a) : "l"(p));
    return a;
}
__device__ __forceinline__ void ldmx4(uint32_t (&r)[4], uint32_t addr) {
    asm volatile("ldmatrix.sync.aligned.m8n8.x4.shared.b16 {%0,%1,%2,%3}, [%4];"
                 : "=r"(r[0]), "=r"(r[1]), "=r"(r[2]), "=r"(r[3]) : "r"(addr));
}
__device__ __forceinline__ void mma16816(float (&d)[4], const uint32_t (&a)[4],
                                         uint32_t b0, uint32_t b1) {
    asm volatile("mma.sync.aligned.m16n8k16.row.col.f32.f16.f16.f32 "
                 "{%0,%1,%2,%3}, {%4,%5,%6,%7}, {%8,%9}, {%0,%1,%2,%3};"
                 : "+f"(d[0]), "+f"(d[1]), "+f"(d[2]), "+f"(d[3])
                 : "r"(a[0]), "r"(a[1]), "r"(a[2]), "r"(a[3]), "r"(b0), "r"(b1));
}
__device__ __forceinline__ void cpasync16(uint32_t s, const void* g) {
    asm volatile("cp.async.cg.shared.global [%0], [%1], 16;" :: "r"(s), "l"(g));
}
__device__ __forceinline__ void cp_commit() {
    asm volatile("cp.async.commit_group;" ::: "memory");
}
__device__ __forceinline__ void cp_wait_all() {
    asm volatile("cp.async.wait_group 0;" ::: "memory");
}
__device__ __forceinline__ uint32_t packh2(float a, float b) {
    __half2 h = __floats2half2_rn(a, b);
    return *(uint32_t*)&h;
}

// ---------------------------------------------------------------------------
// Transpose fp32 [K][N] -> fp16 [N][K]
// ---------------------------------------------------------------------------
__global__ void transpose_to_half(const float* __restrict__ src, __half* __restrict__ dst,
                                  int K, int N) {
    __shared__ float t[32][33];
    const int n0 = blockIdx.x * 32, k0 = blockIdx.y * 32;
    const int tx = threadIdx.x, ty = threadIdx.y;
#pragma unroll
    for (int i = 0; i < 32; i += 8)
        t[ty + i][tx] = src[(size_t)(k0 + ty + i) * N + n0 + tx];
    __syncthreads();
#pragma unroll
    for (int i = 0; i < 32; i += 8)
        dst[(size_t)(n0 + ty + i) * K + k0 + tx] = __float2half_rn(t[tx][ty + i]);
}

// ---------------------------------------------------------------------------
// Brute-force 3-NN + IDW (branchless top-3, float4 SMEM).
// Distance arithmetic identical to the R2-passing version.
// ---------------------------------------------------------------------------
__global__ __launch_bounds__(256) void knn_kernel(const float* __restrict__ xyz_hi,
                                                  const float* __restrict__ xyz_lo) {
    __shared__ float4 P[Sv];
    const int b     = blockIdx.x >> 5;
    const int qbase = (blockIdx.x & 31) * 256;
    const int tid   = threadIdx.x;

    for (int s = tid; s < Sv; s += 256) {
        float x = xyz_lo[((size_t)b * Sv + s) * 3 + 0];
        float y = xyz_lo[((size_t)b * Sv + s) * 3 + 1];
        float z = xyz_lo[((size_t)b * Sv + s) * 3 + 2];
        P[s] = make_float4(x, y, z, fmaf(z, z, fmaf(y, y, x * x)));
    }
    __syncthreads();

    const int q = b * Nv + qbase + tid;
    const float qx = xyz_hi[(size_t)q * 3 + 0];
    const float qy = xyz_hi[(size_t)q * 3 + 1];
    const float qz = xyz_hi[(size_t)q * 3 + 2];
    const float qq = fmaf(qz, qz, fmaf(qy, qy, qx * qx));

    float d0 = 1e30f, d1 = 1e30f, d2 = 1e30f;
    int   i0 = 0,     i1 = 0,     i2 = 0;

#pragma unroll 4
    for (int s = 0; s < Sv; s++) {
        float4 p = P[s];
        float dot = fmaf(qz, p.z, fmaf(qy, p.y, qx * p.x));
        float d   = __fsub_rn(__fadd_rn(qq, p.w), __fmul_rn(2.0f, dot));
        bool l2 = d < d2, l1 = d < d1, l0 = d < d0;
        d2 = l1 ? d1 : (l2 ? d : d2);  i2 = l1 ? i1 : (l2 ? s : i2);
        d1 = l0 ? d0 : (l1 ? d : d1);  i1 = l0 ? i0 : (l1 ? s : i1);
        d0 = l0 ? d  : d0;             i0 = l0 ? s  : i0;
    }

    float r0 = 1.0f / (sqrtf(fmaxf(d0, 0.0f)) + 1e-8f);
    float r1 = 1.0f / (sqrtf(fmaxf(d1, 0.0f)) + 1e-8f);
    float r2 = 1.0f / (sqrtf(fmaxf(d2, 0.0f)) + 1e-8f);
    float inv = 1.0f / (r0 + r1 + r2);
    g_w[(size_t)q * 3 + 0] = r0 * inv;
    g_w[(size_t)q * 3 + 1] = r1 * inv;
    g_w[(size_t)q * 3 + 2] = r2 * inv;
    g_idx[(size_t)q * 3 + 0] = i0;
    g_idx[(size_t)q * 3 + 1] = i1;
    g_idx[(size_t)q * 3 + 2] = i2;
}

// ---------------------------------------------------------------------------
// Fused mma.sync kernel: per CTA one 128x256 output tile, 512 threads.
// Warp grid 4(m) x 4(n); warp tile 32x64; acc[2][8][4] fp32 registers.
// SMEM layout (bytes):
//   PRM 0      : b1,b2,gamma,beta              4096
//   WSM 4096   : 384 floats (IDW weights)      1536
//   ISM 5632   : 384 ints  (KNN idx)           1536
//   A   7424   : 2 x [128][72] half            36864   (also Red/Mu in epi2)
//   B   44288  : 2 x [256][72] half            73728
//   H   118016 : [128][264] half               67584
// total 185600
// ---------------------------------------------------------------------------
#define PRM_OFF  0
#define WSM_OFF  4096
#define ISM_OFF  5632
#define A_OFF    7424
#define A_BYTES  18432
#define B_OFF    44288
#define B_BYTES  36864
#define H_OFF    118016
#define SMEM_TOTAL 185600
#define ASTRIDE  72      // halfs
#define HSTRIDE  264     // halfs

__global__ __launch_bounds__(512, 1) void fused_kernel(
        const float* __restrict__ feat_skip,
        const float* __restrict__ feat_lo,
        const float* __restrict__ b1,
        const float* __restrict__ b2,
        const float* __restrict__ gamma,
        const float* __restrict__ beta,
        float* __restrict__ out) {
    extern __shared__ char sm[];
    const uint32_t sb = smem_u32(sm);

    const int tid    = threadIdx.x;
    const int wid    = tid >> 5;
    const int lane   = tid & 31;
    const int warp_m = wid & 3;
    const int warp_n = wid >> 2;
    const int m0     = blockIdx.x * 128;
    const int bb     = m0 >> 13;

    float* Pb1 = (float*)(sm + PRM_OFF);
    float* Pb2 = Pb1 + 256;
    float* Pg  = Pb1 + 512;
    float* Pbt = Pb1 + 768;
    float* Wsm = (float*)(sm + WSM_OFF);
    int*   Ism = (int*)(sm + ISM_OFF);

    if (tid < 256) {
        Pb1[tid] = b1[tid]; Pb2[tid] = b2[tid];
        Pg[tid]  = gamma[tid]; Pbt[tid] = beta[tid];
    }
    for (int i = tid; i < 384; i += 512) {
        Wsm[i] = g_w[(size_t)m0 * 3 + i];
        Ism[i] = g_idx[(size_t)m0 * 3 + i];
    }
    __syncthreads();

    const uint32_t uA[2] = { sb + A_OFF, sb + A_OFF + A_BYTES };
    const uint32_t uB[2] = { sb + B_OFF, sb + B_OFF + B_BYTES };
    const uint32_t uH    = sb + H_OFF;

    // ldmatrix lane offsets
    const int a_row15 = lane & 15;
    const int a_k8    = (lane & 16) ? 8 : 0;
    const int b_noff  = (lane & 7) + ((lane & 16) ? 8 : 0);
    const int b_k8    = (lane & 8) ? 8 : 0;

    // A builder layout: 16 k-groups x 32 rows, 4 row-iterations
    const int fx = tid & 15;
    const int r0 = tid >> 4;

    float acc[2][8][4];
#pragma unroll
    for (int mt = 0; mt < 2; mt++)
#pragma unroll
        for (int nt = 0; nt < 8; nt++)
#pragma unroll
            for (int e = 0; e < 4; e++) acc[mt][nt][e] = 0.0f;

    // ---- lambdas as macros ----
#define BUILD_A(K0, BUF)                                                              \
    do {                                                                              \
        char* Ab = sm + A_OFF + (BUF) * A_BYTES;                                      \
        if ((K0) < SKIPD) {                                                           \
            _Pragma("unroll")                                                         \
            for (int i = 0; i < 4; i++) {                                             \
                const int row = r0 + i * 32;                                          \
                float4 v = *(const float4*)(feat_skip +                               \
                        (size_t)(m0 + row) * SKIPD + (K0) + fx * 4);                  \
                *(uint2*)(Ab + row * (ASTRIDE * 2) + fx * 8) =                        \
                    make_uint2(packh2(v.x, v.y), packh2(v.z, v.w));                   \
            }                                                                         \
        } else {                                                                      \
            const int kb = (K0) - SKIPD + fx * 4;                                     \
            _Pragma("unroll")                                                         \
            for (int i = 0; i < 4; i++) {                                             \
                const int row = r0 + i * 32;                                          \
                const float w0 = Wsm[row * 3 + 0];                                    \
                const float w1 = Wsm[row * 3 + 1];                                    \
                const float w2 = Wsm[row * 3 + 2];                                    \
                const float* f0 = feat_lo + ((size_t)bb * Sv + Ism[row * 3 + 0]) * LOWD + kb; \
                const float* f1 = feat_lo + ((size_t)bb * Sv + Ism[row * 3 + 1]) * LOWD + kb; \
                const float* f2 = feat_lo + ((size_t)bb * Sv + Ism[row * 3 + 2]) * LOWD + kb; \
                float4 c0 = *(const float4*)f0;                                       \
                float4 c1 = *(const float4*)f1;                                       \
                float4 c2 = *(const float4*)f2;                                       \
                float vx = fmaf(w2, c2.x, fmaf(w1, c1.x, w0 * c0.x));                 \
                float vy = fmaf(w2, c2.y, fmaf(w1, c1.y, w0 * c0.y));                 \
                float vz = fmaf(w2, c2.z, fmaf(w1, c1.z, w0 * c0.z));                 \
                float vw = fmaf(w2, c2.w, fmaf(w1, c1.w, w0 * c0.w));                 \
                *(uint2*)(Ab + row * (ASTRIDE * 2) + fx * 8) =                        \
                    make_uint2(packh2(vx, vy), packh2(vz, vw));                       \
            }                                                                         \
        }                                                                             \
    } while (0)

#define COPY_B(WP, KDIM, K0, BUF)                                                     \
    do {                                                                              \
        const uint32_t Bb = uB[(BUF)];                                                \
        _Pragma("unroll")                                                             \
        for (int j = 0; j < 4; j++) {                                                 \
            const int s = tid + j * 512;                                              \
            const int n = s >> 3, c = s & 7;                                          \
            cpasync16(Bb + n * (ASTRIDE * 2) + c * 16,                                \
                      (const char*)(WP) + ((size_t)n * (KDIM) + (K0)) * 2 + c * 16);  \
        }                                                                             \
    } while (0)

#define MMA_CHUNK(ABASE, ASTR, AKOFF, BBUF)                                           \
    do {                                                                              \
        _Pragma("unroll")                                                             \
        for (int ks = 0; ks < 4; ks++) {                                              \
            uint32_t af[2][4];                                                        \
            _Pragma("unroll")                                                         \
            for (int mt = 0; mt < 2; mt++)                                            \
                ldmx4(af[mt], (ABASE) +                                               \
                      ((warp_m * 32 + mt * 16 + a_row15) * (ASTR) +                   \
                       (AKOFF) + ks * 16 + a_k8) * 2);                                \
            _Pragma("unroll")                                                         \
            for (int p = 0; p < 4; p++) {                                             \
                uint32_t bf[4];                                                       \
                ldmx4(bf, (BBUF) +                                                    \
                      ((warp_n * 64 + p * 16 + b_noff) * ASTRIDE +                    \
                       ks * 16 + b_k8) * 2);                                          \
                mma16816(acc[0][2 * p],     af[0], bf[0], bf[1]);                     \
                mma16816(acc[0][2 * p + 1], af[0], bf[2], bf[3]);                     \
                mma16816(acc[1][2 * p],     af[1], bf[0], bf[1]);                     \
                mma16816(acc[1][2 * p + 1], af[1], bf[2], bf[3]);                     \
            }                                                                         \
        }                                                                             \
    } while (0)

    // ======================= GEMM 1: K = 768 (12 chunks of 64) ===========
    BUILD_A(0, 0);
    COPY_B(g_W1h, IND, 0, 0);
    cp_commit();
    cp_wait_all();
    __syncthreads();

    for (int it = 0; it < 12; it++) {
        const int buf = it & 1;
        if (it < 11) { COPY_B(g_W1h, IND, (it + 1) * 64, buf ^ 1); cp_commit(); }
        MMA_CHUNK(uA[buf], ASTRIDE, 0, uB[buf]);
        if (it < 11) BUILD_A((it + 1) * 64, buf ^ 1);
        cp_wait_all();
        __syncthreads();
    }

    // ======================= Epilogue 1: h = fp16(relu(acc + b1)) ========
    {
        const int rA = warp_m * 32 + (lane >> 2);
        const int cA = warp_n * 64 + (lane & 3) * 2;
#pragma unroll
        for (int mt = 0; mt < 2; mt++)
#pragma unroll
            for (int nt = 0; nt < 8; nt++) {
                const int row = rA + mt * 16;
                const int col = cA + nt * 8;
                float v0 = fmaxf(acc[mt][nt][0] + Pb1[col],     0.0f);
                float v1 = fmaxf(acc[mt][nt][1] + Pb1[col + 1], 0.0f);
                float v2 = fmaxf(acc[mt][nt][2] + Pb1[col],     0.0f);
                float v3 = fmaxf(acc[mt][nt][3] + Pb1[col + 1], 0.0f);
                *(uint32_t*)(sm + H_OFF + (row *     HSTRIDE + col) * 2) = packh2(v0, v1);
                *(uint32_t*)(sm + H_OFF + ((row + 8) * HSTRIDE + col) * 2) = packh2(v2, v3);
            }
    }
    __syncthreads();

    // ======================= GEMM 2: K = 256 (4 chunks of 64) ============
#pragma unroll
    for (int mt = 0; mt < 2; mt++)
#pragma unroll
        for (int nt = 0; nt < 8; nt++)
#pragma unroll
            for (int e = 0; e < 4; e++) acc[mt][nt][e] = 0.0f;

    COPY_B(g_W2h, OUTD, 0, 0);
    cp_commit();
    cp_wait_all();
    __syncthreads();

    for (int it = 0; it < 4; it++) {
        const int buf = it & 1;
        if (it < 3) { COPY_B(g_W2h, OUTD, (it + 1) * 64, buf ^ 1); cp_commit(); }
        MMA_CHUNK(uH, HSTRIDE, it * 64, uB[buf]);
        cp_wait_all();
        __syncthreads();
    }

    // ======================= Epilogue 2: LayerNorm -> out ================
    {
        float* Red  = (float*)(sm + A_OFF);          // [128][4] sums
        float* Red2 = Red + 512;                     // [128][4] sumsq
        float* Mu   = Red2 + 512;                    // [128]
        float* Rs   = Mu + 128;                      // [128]

        const int rA = warp_m * 32 + (lane >> 2);
        const int cA = warp_n * 64 + (lane & 3) * 2;

#pragma unroll
        for (int mt = 0; mt < 2; mt++)
#pragma unroll
            for (int half = 0; half < 2; half++) {
                const int row = rA + mt * 16 + half * 8;
                float s = 0.0f, sq = 0.0f;
#pragma unroll
                for (int nt = 0; nt < 8; nt++) {
                    const int col = cA + nt * 8;
                    float v0 = acc[mt][nt][2 * half]     + Pb2[col];
                    float v1 = acc[mt][nt][2 * half + 1] + Pb2[col + 1];
                    s += v0 + v1;
                    sq = fmaf(v0, v0, fmaf(v1, v1, sq));
                }
                s  += __shfl_xor_sync(0xffffffffu, s, 1);
                s  += __shfl_xor_sync(0xffffffffu, s, 2);
                sq += __shfl_xor_sync(0xffffffffu, sq, 1);
                sq += __shfl_xor_sync(0xffffffffu, sq, 2);
                if ((lane & 3) == 0) {
                    Red[row * 4 + warp_n]  = s;
                    Red2[row * 4 + warp_n] = sq;
                }
            }
        __syncthreads();
        if (tid < 128) {
            float s  = Red[tid * 4]  + Red[tid * 4 + 1]  + Red[tid * 4 + 2]  + Red[tid * 4 + 3];
            float sq = Red2[tid * 4] + Red2[tid * 4 + 1] + Red2[tid * 4 + 2] + Red2[tid * 4 + 3];
            const float mu  = s * (1.0f / 256.0f);
            const float var = fmaxf(sq * (1.0f / 256.0f) - mu * mu, 0.0f);
            Mu[tid] = mu;
            Rs[tid] = rsqrtf(var + 1e-5f);
        }
        __syncthreads();

#pragma unroll
        for (int mt = 0; mt < 2; mt++)
#pragma unroll
            for (int half = 0; half < 2; half++) {
                const int row  = rA + mt * 16 + half * 8;
                const float mu = Mu[row], rstd = Rs[row];
                float* dst = out + (size_t)(m0 + row) * OUTD;
#pragma unroll
                for (int nt = 0; nt < 8; nt++) {
                    const int col = cA + nt * 8;
                    float v0 = acc[mt][nt][2 * half]     + Pb2[col];
                    float v1 = acc[mt][nt][2 * half + 1] + Pb2[col + 1];
                    float2 o;
                    o.x = fmaf((v0 - mu) * rstd, Pg[col],     Pbt[col]);
                    o.y = fmaf((v1 - mu) * rstd, Pg[col + 1], Pbt[col + 1]);
                    *(float2*)(dst + col) = o;
                }
            }
    }
}

// ---------------------------------------------------------------------------
extern "C" void kernel_launch(void* const* d_in, const int* in_sizes, int n_in,
                              void* d_out, int out_size) {
    const float* xyz_hi    = (const float*)d_in[0];
    const float* xyz_lo    = (const float*)d_in[1];
    const float* feat_skip = (const float*)d_in[2];
    const float* feat_lo   = (const float*)d_in[3];
    const float* W1        = (const float*)d_in[4];
    const float* b1        = (const float*)d_in[5];
    const float* W2        = (const float*)d_in[6];
    const float* b2        = (const float*)d_in[7];
    const float* gamma     = (const float*)d_in[8];
    const float* beta      = (const float*)d_in[9];
    float* out = (float*)d_out;

    __half* w1h; cudaGetSymbolAddress((void**)&w1h, g_W1h);
    __half* w2h; cudaGetSymbolAddress((void**)&w2h, g_W2h);

    transpose_to_half<<<dim3(OUTD / 32, IND / 32), dim3(32, 8)>>>(W1, w1h, IND, OUTD);
    transpose_to_half<<<dim3(OUTD / 32, OUTD / 32), dim3(32, 8)>>>(W2, w2h, OUTD, OUTD);
    knn_kernel<<<Bv * (Nv / 256), 256>>>(xyz_hi, xyz_lo);

    cudaFuncSetAttribute(fused_kernel,
                         cudaFuncAttributeMaxDynamicSharedMemorySize, SMEM_TOTAL);
    fused_kernel<<<(Bv * Nv) / 128, 512, SMEM_TOTAL>>>(
        feat_skip, feat_lo, b1, b2, gamma, beta, out);
}

// round 5
// speedup vs baseline: 4.3787x; 1.2163x over previous
#include <cuda_runtime.h>
#include <cuda_fp16.h>
#include <math.h>
#include <stdint.h>

// Problem constants
#define Bv     4
#define Nv     8192
#define Sv     2048
#define LOWD   512
#define SKIPD  256
#define OUTD   256
#define IND    768

// Scratch (device globals; no allocation allowed)
__device__ float  g_w[(size_t)Bv * Nv * 3];
__device__ int    g_idx[(size_t)Bv * Nv * 3];
__device__ __half g_W1h[(size_t)OUTD * IND];    // W1^T fp16 [n][k]
__device__ __half g_W2h[(size_t)OUTD * OUTD];   // W2^T fp16 [n][k]
__device__ float  g_G[(size_t)Bv * Sv * OUTD];  // feat_lo @ W1[256:]  (8 MB)

// ---------------------------------------------------------------------------
// Helpers (family-portable: ldmatrix / mma.sync / cp.async only)
// ---------------------------------------------------------------------------
__device__ __forceinline__ uint32_t smem_u32(const void* p) {
    uint32_t a;
    asm("{ .reg .u64 t; cvta.to.shared.u64 t, %1; cvt.u32.u64 %0, t; }"
        : "=r"(a) : "l"(p));
    return a;
}
__device__ __forceinline__ void ldmx4(uint32_t (&r)[4], uint32_t addr) {
    asm volatile("ldmatrix.sync.aligned.m8n8.x4.shared.b16 {%0,%1,%2,%3}, [%4];"
                 : "=r"(r[0]), "=r"(r[1]), "=r"(r[2]), "=r"(r[3]) : "r"(addr));
}
__device__ __forceinline__ void mma16816(float (&d)[4], const uint32_t (&a)[4],
                                         uint32_t b0, uint32_t b1) {
    asm volatile("mma.sync.aligned.m16n8k16.row.col.f32.f16.f16.f32 "
                 "{%0,%1,%2,%3}, {%4,%5,%6,%7}, {%8,%9}, {%0,%1,%2,%3};"
                 : "+f"(d[0]), "+f"(d[1]), "+f"(d[2]), "+f"(d[3])
                 : "r"(a[0]), "r"(a[1]), "r"(a[2]), "r"(a[3]), "r"(b0), "r"(b1));
}
__device__ __forceinline__ void cpasync16(uint32_t s, const void* g) {
    asm volatile("cp.async.cg.shared.global [%0], [%1], 16;" :: "r"(s), "l"(g));
}
__device__ __forceinline__ void cp_commit() {
    asm volatile("cp.async.commit_group;" ::: "memory");
}
__device__ __forceinline__ void cp_wait_all() {
    asm volatile("cp.async.wait_group 0;" ::: "memory");
}
__device__ __forceinline__ uint32_t packh2(float a, float b) {
    __half2 h = __floats2half2_rn(a, b);
    return *(uint32_t*)&h;
}

#define ASTRIDE  72      // halfs
#define HSTRIDE  264     // halfs

// ---------------------------------------------------------------------------
// Transposes (merged): fp32 [K][N] -> fp16 [N][K] for W1 (K=768) and W2 (K=256)
// grid = (8, 24 + 8), block = (32, 8)
// ---------------------------------------------------------------------------
__global__ void transpose_both(const float* __restrict__ W1, const float* __restrict__ W2,
                               __half* __restrict__ w1h, __half* __restrict__ w2h) {
    __shared__ float t[32][33];
    const int tx = threadIdx.x, ty = threadIdx.y;
    const float* src; __half* dst; int K, k0;
    if (blockIdx.y < 24) { src = W1; dst = w1h; K = IND;  k0 = blockIdx.y * 32; }
    else                 { src = W2; dst = w2h; K = OUTD; k0 = (blockIdx.y - 24) * 32; }
    const int n0 = blockIdx.x * 32;
#pragma unroll
    for (int i = 0; i < 32; i += 8)
        t[ty + i][tx] = src[(size_t)(k0 + ty + i) * OUTD + n0 + tx];
    __syncthreads();
#pragma unroll
    for (int i = 0; i < 32; i += 8)
        dst[(size_t)(n0 + ty + i) * K + k0 + tx] = __float2half_rn(t[tx][ty + i]);
}

// ---------------------------------------------------------------------------
// Brute-force 3-NN + IDW. Fast path: min-of-4 vs current 3rd-best, rare insert.
// qq dropped from the scanned metric (argmin-invariant), re-added for weights.
// ---------------------------------------------------------------------------
__global__ __launch_bounds__(256) void knn_kernel(const float* __restrict__ xyz_hi,
                                                  const float* __restrict__ xyz_lo) {
    __shared__ float4 P[Sv];
    const int b     = blockIdx.x >> 5;
    const int qbase = (blockIdx.x & 31) * 256;
    const int tid   = threadIdx.x;

    for (int s = tid; s < Sv; s += 256) {
        float x = xyz_lo[((size_t)b * Sv + s) * 3 + 0];
        float y = xyz_lo[((size_t)b * Sv + s) * 3 + 1];
        float z = xyz_lo[((size_t)b * Sv + s) * 3 + 2];
        P[s] = make_float4(x, y, z, fmaf(z, z, fmaf(y, y, x * x)));
    }
    __syncthreads();

    const int q = b * Nv + qbase + tid;
    const float qx = xyz_hi[(size_t)q * 3 + 0];
    const float qy = xyz_hi[(size_t)q * 3 + 1];
    const float qz = xyz_hi[(size_t)q * 3 + 2];
    const float qq = fmaf(qz, qz, fmaf(qy, qy, qx * qx));

    float d0 = 1e30f, d1 = 1e30f, d2 = 1e30f;
    int   i0 = 0,     i1 = 0,     i2 = 0;

#define INS3(E, S)                                                     \
    {                                                                  \
        bool l2 = (E) < d2, l1 = (E) < d1, l0 = (E) < d0;              \
        d2 = l1 ? d1 : (l2 ? (E) : d2);  i2 = l1 ? i1 : (l2 ? (S) : i2); \
        d1 = l0 ? d0 : (l1 ? (E) : d1);  i1 = l0 ? i0 : (l1 ? (S) : i1); \
        d0 = l0 ? (E) : d0;              i0 = l0 ? (S) : i0;           \
    }

    for (int s = 0; s < Sv; s += 4) {
        float4 p0 = P[s + 0], p1 = P[s + 1], p2 = P[s + 2], p3 = P[s + 3];
        float e0 = fmaf(-2.0f, fmaf(qz, p0.z, fmaf(qy, p0.y, qx * p0.x)), p0.w);
        float e1 = fmaf(-2.0f, fmaf(qz, p1.z, fmaf(qy, p1.y, qx * p1.x)), p1.w);
        float e2 = fmaf(-2.0f, fmaf(qz, p2.z, fmaf(qy, p2.y, qx * p2.x)), p2.w);
        float e3 = fmaf(-2.0f, fmaf(qz, p3.z, fmaf(qy, p3.y, qx * p3.x)), p3.w);
        float m = fminf(fminf(e0, e1), fminf(e2, e3));
        if (m < d2) {
            INS3(e0, s + 0); INS3(e1, s + 1); INS3(e2, s + 2); INS3(e3, s + 3);
        }
    }
#undef INS3

    float r0 = 1.0f / (sqrtf(fmaxf(d0 + qq, 0.0f)) + 1e-8f);
    float r1 = 1.0f / (sqrtf(fmaxf(d1 + qq, 0.0f)) + 1e-8f);
    float r2 = 1.0f / (sqrtf(fmaxf(d2 + qq, 0.0f)) + 1e-8f);
    float inv = 1.0f / (r0 + r1 + r2);
    g_w[(size_t)q * 3 + 0] = r0 * inv;
    g_w[(size_t)q * 3 + 1] = r1 * inv;
    g_w[(size_t)q * 3 + 2] = r2 * inv;
    g_idx[(size_t)q * 3 + 0] = i0;
    g_idx[(size_t)q * 3 + 1] = i1;
    g_idx[(size_t)q * 3 + 2] = i2;
}

// ---------------------------------------------------------------------------
// GEMM-G: G = feat_lo[8192 x 512] @ W1[256:]^T -> fp32 [8192][256]
// 128 CTAs (M-tile 64), 256 threads, warp grid 2m x 4n, warp tile 32x64.
// ---------------------------------------------------------------------------
#define GA_BYTES 9216     // 64 * 72 * 2
#define GB_BYTES 36864    // 256 * 72 * 2
#define GSMEM    (2 * GA_BYTES + 2 * GB_BYTES)

__global__ __launch_bounds__(256, 1) void gemm_g_kernel(const float* __restrict__ feat_lo) {
    extern __shared__ char sm[];
    const uint32_t sb = smem_u32(sm);
    const int tid    = threadIdx.x;
    const int wid    = tid >> 5;
    const int lane   = tid & 31;
    const int warp_m = wid & 1;
    const int warp_n = wid >> 1;
    const int g0     = blockIdx.x * 64;

    const uint32_t uA[2] = { sb, sb + GA_BYTES };
    const uint32_t uB[2] = { sb + 2 * GA_BYTES, sb + 2 * GA_BYTES + GB_BYTES };

    const int a_row15 = lane & 15;
    const int a_k8    = (lane & 16) ? 8 : 0;
    const int b_noff  = (lane & 7) + ((lane & 16) ? 8 : 0);
    const int b_k8    = (lane & 8) ? 8 : 0;
    const int fx = tid & 15, r0 = tid >> 4;

    float acc[2][8][4];
#pragma unroll
    for (int mt = 0; mt < 2; mt++)
#pragma unroll
        for (int nt = 0; nt < 8; nt++)
#pragma unroll
            for (int e = 0; e < 4; e++) acc[mt][nt][e] = 0.0f;

#define GBUILD_A(K0, BUF)                                                         \
    do {                                                                          \
        char* Ab = sm + (BUF) * GA_BYTES;                                         \
        _Pragma("unroll")                                                         \
        for (int i = 0; i < 4; i++) {                                             \
            const int row = r0 + i * 16;                                          \
            float4 v = *(const float4*)(feat_lo + (size_t)(g0 + row) * LOWD + (K0) + fx * 4); \
            *(uint2*)(Ab + row * (ASTRIDE * 2) + fx * 8) =                        \
                make_uint2(packh2(v.x, v.y), packh2(v.z, v.w));                   \
        }                                                                         \
    } while (0)

#define GCOPY_B(K0, BUF)                                                          \
    do {                                                                          \
        const uint32_t Bb = uB[(BUF)];                                            \
        _Pragma("unroll")                                                         \
        for (int j = 0; j < 8; j++) {                                             \
            const int s = tid + j * 256;                                          \
            const int n = s >> 3, c = s & 7;                                      \
            cpasync16(Bb + n * (ASTRIDE * 2) + c * 16,                            \
                      (const char*)g_W1h + ((size_t)n * IND + SKIPD + (K0)) * 2 + c * 16); \
        }                                                                         \
    } while (0)

    GBUILD_A(0, 0);
    GCOPY_B(0, 0);
    cp_commit();
    cp_wait_all();
    __syncthreads();

    for (int it = 0; it < 8; it++) {
        const int buf = it & 1;
        if (it < 7) { GCOPY_B((it + 1) * 64, buf ^ 1); cp_commit(); }
#pragma unroll
        for (int ks = 0; ks < 4; ks++) {
            uint32_t af[2][4];
#pragma unroll
            for (int mt = 0; mt < 2; mt++)
                ldmx4(af[mt], uA[buf] +
                      ((warp_m * 32 + mt * 16 + a_row15) * ASTRIDE + ks * 16 + a_k8) * 2);
#pragma unroll
            for (int p = 0; p < 4; p++) {
                uint32_t bf[4];
                ldmx4(bf, uB[buf] +
                      ((warp_n * 64 + p * 16 + b_noff) * ASTRIDE + ks * 16 + b_k8) * 2);
                mma16816(acc[0][2 * p],     af[0], bf[0], bf[1]);
                mma16816(acc[0][2 * p + 1], af[0], bf[2], bf[3]);
                mma16816(acc[1][2 * p],     af[1], bf[0], bf[1]);
                mma16816(acc[1][2 * p + 1], af[1], bf[2], bf[3]);
            }
        }
        if (it < 7) GBUILD_A((it + 1) * 64, buf ^ 1);
        cp_wait_all();
        __syncthreads();
    }

    const int rA = warp_m * 32 + (lane >> 2);
    const int cA = warp_n * 64 + (lane & 3) * 2;
#pragma unroll
    for (int mt = 0; mt < 2; mt++)
#pragma unroll
        for (int hf = 0; hf < 2; hf++) {
            const int row = rA + mt * 16 + hf * 8;
            float* dst = g_G + (size_t)(g0 + row) * OUTD;
#pragma unroll
            for (int nt = 0; nt < 8; nt++) {
                const int col = cA + nt * 8;
                float2 o = make_float2(acc[mt][nt][2 * hf], acc[mt][nt][2 * hf + 1]);
                *(float2*)(dst + col) = o;
            }
        }
}

// ---------------------------------------------------------------------------
// Fused kernel: 128x256 tile, 512 threads, warp grid 4m x 4n.
//   GEMM1: feat_skip[128x256]h @ W1top^T -> acc
//   epi1 : acc += b1 + IDW-gather(G); relu -> H (fp16 smem)
//   GEMM2: H @ W2^T -> acc
//   epi2 : LayerNorm -> out
// ---------------------------------------------------------------------------
#define PRM_OFF  0
#define WSM_OFF  4096
#define ISM_OFF  5632
#define A_OFF    7424
#define A_BYTES  18432
#define B_OFF    44288
#define B_BYTES  36864
#define H_OFF    118016
#define SMEM_TOTAL 185600

__global__ __launch_bounds__(512, 1) void fused_kernel(
        const float* __restrict__ feat_skip,
        const float* __restrict__ b1,
        const float* __restrict__ b2,
        const float* __restrict__ gamma,
        const float* __restrict__ beta,
        float* __restrict__ out) {
    extern __shared__ char sm[];
    const uint32_t sb = smem_u32(sm);

    const int tid    = threadIdx.x;
    const int wid    = tid >> 5;
    const int lane   = tid & 31;
    const int warp_m = wid & 3;
    const int warp_n = wid >> 2;
    const int m0     = blockIdx.x * 128;
    const int bb     = m0 >> 13;

    float* Pb1 = (float*)(sm + PRM_OFF);
    float* Pb2 = Pb1 + 256;
    float* Pg  = Pb1 + 512;
    float* Pbt = Pb1 + 768;
    float* Wsm = (float*)(sm + WSM_OFF);
    int*   Ism = (int*)(sm + ISM_OFF);

    if (tid < 256) {
        Pb1[tid] = b1[tid]; Pb2[tid] = b2[tid];
        Pg[tid]  = gamma[tid]; Pbt[tid] = beta[tid];
    }
    for (int i = tid; i < 384; i += 512) {
        Wsm[i] = g_w[(size_t)m0 * 3 + i];
        Ism[i] = g_idx[(size_t)m0 * 3 + i];
    }
    __syncthreads();

    const uint32_t uA[2] = { sb + A_OFF, sb + A_OFF + A_BYTES };
    const uint32_t uB[2] = { sb + B_OFF, sb + B_OFF + B_BYTES };
    const uint32_t uH    = sb + H_OFF;

    const int a_row15 = lane & 15;
    const int a_k8    = (lane & 16) ? 8 : 0;
    const int b_noff  = (lane & 7) + ((lane & 16) ? 8 : 0);
    const int b_k8    = (lane & 8) ? 8 : 0;
    const int fx = tid & 15, r0 = tid >> 4;

    float acc[2][8][4];
#pragma unroll
    for (int mt = 0; mt < 2; mt++)
#pragma unroll
        for (int nt = 0; nt < 8; nt++)
#pragma unroll
            for (int e = 0; e < 4; e++) acc[mt][nt][e] = 0.0f;

#define BUILD_A(K0, BUF)                                                          \
    do {                                                                          \
        char* Ab = sm + A_OFF + (BUF) * A_BYTES;                                  \
        _Pragma("unroll")                                                         \
        for (int i = 0; i < 4; i++) {                                             \
            const int row = r0 + i * 32;                                          \
            float4 v = *(const float4*)(feat_skip +                               \
                    (size_t)(m0 + row) * SKIPD + (K0) + fx * 4);                  \
            *(uint2*)(Ab + row * (ASTRIDE * 2) + fx * 8) =                        \
                make_uint2(packh2(v.x, v.y), packh2(v.z, v.w));                   \
        }                                                                         \
    } while (0)

#define COPY_B(WP, KDIM, K0, BUF)                                                 \
    do {                                                                          \
        const uint32_t Bb = uB[(BUF)];                                            \
        _Pragma("unroll")                                                         \
        for (int j = 0; j < 4; j++) {                                             \
            const int s = tid + j * 512;                                          \
            const int n = s >> 3, c = s & 7;                                      \
            cpasync16(Bb + n * (ASTRIDE * 2) + c * 16,                            \
                      (const char*)(WP) + ((size_t)n * (KDIM) + (K0)) * 2 + c * 16); \
        }                                                                         \
    } while (0)

#define MMA_CHUNK(ABASE, ASTR, AKOFF, BBUF)                                       \
    do {                                                                          \
        _Pragma("unroll")                                                         \
        for (int ks = 0; ks < 4; ks++) {                                          \
            uint32_t af[2][4];                                                    \
            _Pragma("unroll")                                                     \
            for (int mt = 0; mt < 2; mt++)                                        \
                ldmx4(af[mt], (ABASE) +                                           \
                      ((warp_m * 32 + mt * 16 + a_row15) * (ASTR) +               \
                       (AKOFF) + ks * 16 + a_k8) * 2);                            \
            _Pragma("unroll")                                                     \
            for (int p = 0; p < 4; p++) {                                         \
                uint32_t bf[4];                                                   \
                ldmx4(bf, (BBUF) +                                                \
                      ((warp_n * 64 + p * 16 + b_noff) * ASTRIDE +                \
                       ks * 16 + b_k8) * 2);                                      \
                mma16816(acc[0][2 * p],     af[0], bf[0], bf[1]);                 \
                mma16816(acc[0][2 * p + 1], af[0], bf[2], bf[3]);                 \
                mma16816(acc[1][2 * p],     af[1], bf[0], bf[1]);                 \
                mma16816(acc[1][2 * p + 1], af[1], bf[2], bf[3]);                 \
            }                                                                     \
        }                                                                         \
    } while (0)

    // ======================= GEMM 1: K = 256 (4 chunks) ==================
    BUILD_A(0, 0);
    COPY_B(g_W1h, IND, 0, 0);
    cp_commit();
    cp_wait_all();
    __syncthreads();

    for (int it = 0; it < 4; it++) {
        const int buf = it & 1;
        if (it < 3) { COPY_B(g_W1h, IND, (it + 1) * 64, buf ^ 1); cp_commit(); }
        MMA_CHUNK(uA[buf], ASTRIDE, 0, uB[buf]);
        if (it < 3) BUILD_A((it + 1) * 64, buf ^ 1);
        cp_wait_all();
        __syncthreads();
    }

    // ========= Epilogue 1: acc += b1 + IDW(G); relu; -> H fp16 ===========
    {
        const int rA = warp_m * 32 + (lane >> 2);
        const int cA = warp_n * 64 + (lane & 3) * 2;
#pragma unroll
        for (int mt = 0; mt < 2; mt++)
#pragma unroll
            for (int hf = 0; hf < 2; hf++) {
                const int row = rA + mt * 16 + hf * 8;
                const float w0 = Wsm[row * 3 + 0];
                const float w1 = Wsm[row * 3 + 1];
                const float w2 = Wsm[row * 3 + 2];
                const float* G0 = g_G + ((size_t)bb * Sv + Ism[row * 3 + 0]) * OUTD;
                const float* G1 = g_G + ((size_t)bb * Sv + Ism[row * 3 + 1]) * OUTD;
                const float* G2 = g_G + ((size_t)bb * Sv + Ism[row * 3 + 2]) * OUTD;
#pragma unroll
                for (int nt = 0; nt < 8; nt++) {
                    const int col = cA + nt * 8;
                    float2 a0 = *(const float2*)(G0 + col);
                    float2 a1 = *(const float2*)(G1 + col);
                    float2 a2 = *(const float2*)(G2 + col);
                    float v0 = acc[mt][nt][2 * hf]     + Pb1[col];
                    float v1 = acc[mt][nt][2 * hf + 1] + Pb1[col + 1];
                    v0 = fmaf(w0, a0.x, fmaf(w1, a1.x, fmaf(w2, a2.x, v0)));
                    v1 = fmaf(w0, a0.y, fmaf(w1, a1.y, fmaf(w2, a2.y, v1)));
                    v0 = fmaxf(v0, 0.0f);
                    v1 = fmaxf(v1, 0.0f);
                    *(uint32_t*)(sm + H_OFF + (row * HSTRIDE + col) * 2) = packh2(v0, v1);
                }
            }
    }
    __syncthreads();

    // ======================= GEMM 2: K = 256 (4 chunks) ==================
#pragma unroll
    for (int mt = 0; mt < 2; mt++)
#pragma unroll
        for (int nt = 0; nt < 8; nt++)
#pragma unroll
            for (int e = 0; e < 4; e++) acc[mt][nt][e] = 0.0f;

    COPY_B(g_W2h, OUTD, 0, 0);
    cp_commit();
    cp_wait_all();
    __syncthreads();

    for (int it = 0; it < 4; it++) {
        const int buf = it & 1;
        if (it < 3) { COPY_B(g_W2h, OUTD, (it + 1) * 64, buf ^ 1); cp_commit(); }
        MMA_CHUNK(uH, HSTRIDE, it * 64, uB[buf]);
        cp_wait_all();
        __syncthreads();
    }

    // ======================= Epilogue 2: LayerNorm -> out ================
    {
        float* Red  = (float*)(sm + A_OFF);
        float* Red2 = Red + 512;
        float* Mu   = Red2 + 512;
        float* Rs   = Mu + 128;

        const int rA = warp_m * 32 + (lane >> 2);
        const int cA = warp_n * 64 + (lane & 3) * 2;

#pragma unroll
        for (int mt = 0; mt < 2; mt++)
#pragma unroll
            for (int hf = 0; hf < 2; hf++) {
                const int row = rA + mt * 16 + hf * 8;
                float s = 0.0f, sq = 0.0f;
#pragma unroll
                for (int nt = 0; nt < 8; nt++) {
                    const int col = cA + nt * 8;
                    float v0 = acc[mt][nt][2 * hf]     + Pb2[col];
                    float v1 = acc[mt][nt][2 * hf + 1] + Pb2[col + 1];
                    s += v0 + v1;
                    sq = fmaf(v0, v0, fmaf(v1, v1, sq));
                }
                s  += __shfl_xor_sync(0xffffffffu, s, 1);
                s  += __shfl_xor_sync(0xffffffffu, s, 2);
                sq += __shfl_xor_sync(0xffffffffu, sq, 1);
                sq += __shfl_xor_sync(0xffffffffu, sq, 2);
                if ((lane & 3) == 0) {
                    Red[row * 4 + warp_n]  = s;
                    Red2[row * 4 + warp_n] = sq;
                }
            }
        __syncthreads();
        if (tid < 128) {
            float s  = Red[tid * 4]  + Red[tid * 4 + 1]  + Red[tid * 4 + 2]  + Red[tid * 4 + 3];
            float sq = Red2[tid * 4] + Red2[tid * 4 + 1] + Red2[tid * 4 + 2] + Red2[tid * 4 + 3];
            const float mu  = s * (1.0f / 256.0f);
            const float var = fmaxf(sq * (1.0f / 256.0f) - mu * mu, 0.0f);
            Mu[tid] = mu;
            Rs[tid] = rsqrtf(var + 1e-5f);
        }
        __syncthreads();

#pragma unroll
        for (int mt = 0; mt < 2; mt++)
#pragma unroll
            for (int hf = 0; hf < 2; hf++) {
                const int row  = rA + mt * 16 + hf * 8;
                const float mu = Mu[row], rstd = Rs[row];
                float* dst = out + (size_t)(m0 + row) * OUTD;
#pragma unroll
                for (int nt = 0; nt < 8; nt++) {
                    const int col = cA + nt * 8;
                    float v0 = acc[mt][nt][2 * hf]     + Pb2[col];
                    float v1 = acc[mt][nt][2 * hf + 1] + Pb2[col + 1];
                    float2 o;
                    o.x = fmaf((v0 - mu) * rstd, Pg[col],     Pbt[col]);
                    o.y = fmaf((v1 - mu) * rstd, Pg[col + 1], Pbt[col + 1]);
                    *(float2*)(dst + col) = o;
                }
            }
    }
}

// ---------------------------------------------------------------------------
extern "C" void kernel_launch(void* const* d_in, const int* in_sizes, int n_in,
                              void* d_out, int out_size) {
    const float* xyz_hi    = (const float*)d_in[0];
    const float* xyz_lo    = (const float*)d_in[1];
    const float* feat_skip = (const float*)d_in[2];
    const float* feat_lo   = (const float*)d_in[3];
    const float* W1        = (const float*)d_in[4];
    const float* b1        = (const float*)d_in[5];
    const float* W2        = (const float*)d_in[6];
    const float* b2        = (const float*)d_in[7];
    const float* gamma     = (const float*)d_in[8];
    const float* beta      = (const float*)d_in[9];
    float* out = (float*)d_out;

    __half* w1h; cudaGetSymbolAddress((void**)&w1h, g_W1h);
    __half* w2h; cudaGetSymbolAddress((void**)&w2h, g_W2h);

    transpose_both<<<dim3(8, 32), dim3(32, 8)>>>(W1, W2, w1h, w2h);
    knn_kernel<<<Bv * (Nv / 256), 256>>>(xyz_hi, xyz_lo);

    cudaFuncSetAttribute(gemm_g_kernel,
                         cudaFuncAttributeMaxDynamicSharedMemorySize, GSMEM);
    gemm_g_kernel<<<(Bv * Sv) / 64, 256, GSMEM>>>(feat_lo);

    cudaFuncSetAttribute(fused_kernel,
                         cudaFuncAttributeMaxDynamicSharedMemorySize, SMEM_TOTAL);
    fused_kernel<<<(Bv * Nv) / 128, 512, SMEM_TOTAL>>>(
        feat_skip, b1, b2, gamma, beta, out);
}

// round 6
// speedup vs baseline: 5.0325x; 1.1493x over previous
#include <cuda_runtime.h>
#include <cuda_fp16.h>
#include <math.h>
#include <stdint.h>

// Problem constants
#define Bv     4
#define Nv     8192
#define Sv     2048
#define LOWD   512
#define SKIPD  256
#define OUTD   256
#define IND    768

// Scratch (device globals; no allocation allowed)
__device__ float  g_w[(size_t)Bv * Nv * 3];
__device__ int    g_idx[(size_t)Bv * Nv * 3];
__device__ __half g_W1h[(size_t)OUTD * IND];     // W1^T fp16 [n][k]
__device__ __half g_W2h[(size_t)OUTD * OUTD];    // W2^T fp16 [n][k]
__device__ __half g_Gh[(size_t)Bv * Sv * OUTD];  // feat_lo @ W1[256:] (fp16, 4 MB)

// ---------------------------------------------------------------------------
// Helpers
// ---------------------------------------------------------------------------
__device__ __forceinline__ uint32_t smem_u32(const void* p) {
    uint32_t a;
    asm("{ .reg .u64 t; cvta.to.shared.u64 t, %1; cvt.u32.u64 %0, t; }"
        : "=r"(a) : "l"(p));
    return a;
}
__device__ __forceinline__ void ldmx4(uint32_t (&r)[4], uint32_t addr) {
    asm volatile("ldmatrix.sync.aligned.m8n8.x4.shared.b16 {%0,%1,%2,%3}, [%4];"
                 : "=r"(r[0]), "=r"(r[1]), "=r"(r[2]), "=r"(r[3]) : "r"(addr));
}
__device__ __forceinline__ void mma16816(float (&d)[4], const uint32_t (&a)[4],
                                         uint32_t b0, uint32_t b1) {
    asm volatile("mma.sync.aligned.m16n8k16.row.col.f32.f16.f16.f32 "
                 "{%0,%1,%2,%3}, {%4,%5,%6,%7}, {%8,%9}, {%0,%1,%2,%3};"
                 : "+f"(d[0]), "+f"(d[1]), "+f"(d[2]), "+f"(d[3])
                 : "r"(a[0]), "r"(a[1]), "r"(a[2]), "r"(a[3]), "r"(b0), "r"(b1));
}
__device__ __forceinline__ void cpasync16(uint32_t s, const void* g) {
    asm volatile("cp.async.cg.shared.global [%0], [%1], 16;" :: "r"(s), "l"(g));
}
__device__ __forceinline__ void cp_commit() {
    asm volatile("cp.async.commit_group;" ::: "memory");
}
__device__ __forceinline__ void cp_wait_all() {
    asm volatile("cp.async.wait_group 0;" ::: "memory");
}
__device__ __forceinline__ uint32_t packh2(float a, float b) {
    __half2 h = __floats2half2_rn(a, b);
    return *(uint32_t*)&h;
}

#define ASTRIDE  72      // halfs
#define HSTRIDE  264     // halfs

// ---------------------------------------------------------------------------
// Transposes: fp32 [K][N] -> fp16 [N][K] for W1 (K=768) and W2 (K=256)
// ---------------------------------------------------------------------------
__global__ void transpose_both(const float* __restrict__ W1, const float* __restrict__ W2,
                               __half* __restrict__ w1h, __half* __restrict__ w2h) {
    __shared__ float t[32][33];
    const int tx = threadIdx.x, ty = threadIdx.y;
    const float* src; __half* dst; int K, k0;
    if (blockIdx.y < 24) { src = W1; dst = w1h; K = IND;  k0 = blockIdx.y * 32; }
    else                 { src = W2; dst = w2h; K = OUTD; k0 = (blockIdx.y - 24) * 32; }
    const int n0 = blockIdx.x * 32;
#pragma unroll
    for (int i = 0; i < 32; i += 8)
        t[ty + i][tx] = src[(size_t)(k0 + ty + i) * OUTD + n0 + tx];
    __syncthreads();
#pragma unroll
    for (int i = 0; i < 32; i += 8)
        dst[(size_t)(n0 + ty + i) * K + k0 + tx] = __float2half_rn(t[tx][ty + i]);
}

// ---------------------------------------------------------------------------
// PREP kernel: blocks 0..127 = KNN, blocks 128..255 = GEMM-G.
// ---------------------------------------------------------------------------
#define GA_BYTES 9216     // 64 * 72 * 2
#define GB_BYTES 36864    // 256 * 72 * 2
#define GSMEM    (2 * GA_BYTES + 2 * GB_BYTES)   // 92160

__device__ __forceinline__ void knn_body(char* sm,
                                         const float* __restrict__ xyz_hi,
                                         const float* __restrict__ xyz_lo) {
    float4* P = (float4*)sm;   // 32 KB
    const int bid   = blockIdx.x;
    const int b     = bid >> 5;
    const int qbase = (bid & 31) * 256;
    const int tid   = threadIdx.x;

    for (int s = tid; s < Sv; s += 256) {
        float x = xyz_lo[((size_t)b * Sv + s) * 3 + 0];
        float y = xyz_lo[((size_t)b * Sv + s) * 3 + 1];
        float z = xyz_lo[((size_t)b * Sv + s) * 3 + 2];
        // fold -2 into the stored point; w = |p|^2 so e = pp - 2*dot (3 FMAs)
        P[s] = make_float4(-2.0f * x, -2.0f * y, -2.0f * z,
                           fmaf(z, z, fmaf(y, y, x * x)));
    }
    __syncthreads();

    const int q = b * Nv + qbase + tid;
    const float qx = xyz_hi[(size_t)q * 3 + 0];
    const float qy = xyz_hi[(size_t)q * 3 + 1];
    const float qz = xyz_hi[(size_t)q * 3 + 2];
    const float qq = fmaf(qz, qz, fmaf(qy, qy, qx * qx));

    float d0 = 1e30f, d1 = 1e30f, d2 = 1e30f;
    int   i0 = 0,     i1 = 0,     i2 = 0;

#define INS3(E, S)                                                       \
    {                                                                    \
        bool l2 = (E) < d2, l1 = (E) < d1, l0 = (E) < d0;                \
        d2 = l1 ? d1 : (l2 ? (E) : d2);  i2 = l1 ? i1 : (l2 ? (S) : i2); \
        d1 = l0 ? d0 : (l1 ? (E) : d1);  i1 = l0 ? i0 : (l1 ? (S) : i1); \
        d0 = l0 ? (E) : d0;              i0 = l0 ? (S) : i0;             \
    }
    for (int s = 0; s < Sv; s += 4) {
        float4 p0 = P[s + 0], p1 = P[s + 1], p2 = P[s + 2], p3 = P[s + 3];
        float e0 = fmaf(qx, p0.x, fmaf(qy, p0.y, fmaf(qz, p0.z, p0.w)));
        float e1 = fmaf(qx, p1.x, fmaf(qy, p1.y, fmaf(qz, p1.z, p1.w)));
        float e2 = fmaf(qx, p2.x, fmaf(qy, p2.y, fmaf(qz, p2.z, p2.w)));
        float e3 = fmaf(qx, p3.x, fmaf(qy, p3.y, fmaf(qz, p3.z, p3.w)));
        float m = fminf(fminf(e0, e1), fminf(e2, e3));
        if (m < d2) {
            INS3(e0, s + 0); INS3(e1, s + 1); INS3(e2, s + 2); INS3(e3, s + 3);
        }
    }
#undef INS3

    float r0 = 1.0f / (sqrtf(fmaxf(d0 + qq, 0.0f)) + 1e-8f);
    float r1 = 1.0f / (sqrtf(fmaxf(d1 + qq, 0.0f)) + 1e-8f);
    float r2 = 1.0f / (sqrtf(fmaxf(d2 + qq, 0.0f)) + 1e-8f);
    float inv = 1.0f / (r0 + r1 + r2);
    g_w[(size_t)q * 3 + 0] = r0 * inv;
    g_w[(size_t)q * 3 + 1] = r1 * inv;
    g_w[(size_t)q * 3 + 2] = r2 * inv;
    g_idx[(size_t)q * 3 + 0] = i0;
    g_idx[(size_t)q * 3 + 1] = i1;
    g_idx[(size_t)q * 3 + 2] = i2;
}

__device__ __forceinline__ void gemm_g_body(char* sm, const float* __restrict__ feat_lo) {
    const uint32_t sb = smem_u32(sm);
    const int tid    = threadIdx.x;
    const int wid    = tid >> 5;
    const int lane   = tid & 31;
    const int warp_m = wid & 1;
    const int warp_n = wid >> 1;
    const int g0     = (blockIdx.x - 128) * 64;

    const uint32_t uA[2] = { sb, sb + GA_BYTES };
    const uint32_t uB[2] = { sb + 2 * GA_BYTES, sb + 2 * GA_BYTES + GB_BYTES };

    const int a_row15 = lane & 15;
    const int a_k8    = (lane & 16) ? 8 : 0;
    const int b_noff  = (lane & 7) + ((lane & 16) ? 8 : 0);
    const int b_k8    = (lane & 8) ? 8 : 0;
    const int fx = tid & 15, r0 = tid >> 4;

    float acc[2][8][4];
#pragma unroll
    for (int mt = 0; mt < 2; mt++)
#pragma unroll
        for (int nt = 0; nt < 8; nt++)
#pragma unroll
            for (int e = 0; e < 4; e++) acc[mt][nt][e] = 0.0f;

#define GBUILD_A(K0, BUF)                                                         \
    do {                                                                          \
        char* Ab = sm + (BUF) * GA_BYTES;                                         \
        _Pragma("unroll")                                                         \
        for (int i = 0; i < 4; i++) {                                             \
            const int row = r0 + i * 16;                                          \
            float4 v = *(const float4*)(feat_lo + (size_t)(g0 + row) * LOWD + (K0) + fx * 4); \
            *(uint2*)(Ab + row * (ASTRIDE * 2) + fx * 8) =                        \
                make_uint2(packh2(v.x, v.y), packh2(v.z, v.w));                   \
        }                                                                         \
    } while (0)

#define GCOPY_B(K0, BUF)                                                          \
    do {                                                                          \
        const uint32_t Bb = uB[(BUF)];                                            \
        _Pragma("unroll")                                                         \
        for (int j = 0; j < 8; j++) {                                             \
            const int s = tid + j * 256;                                          \
            const int n = s >> 3, c = s & 7;                                      \
            cpasync16(Bb + n * (ASTRIDE * 2) + c * 16,                            \
                      (const char*)g_W1h + ((size_t)n * IND + SKIPD + (K0)) * 2 + c * 16); \
        }                                                                         \
    } while (0)

    GBUILD_A(0, 0);
    GCOPY_B(0, 0);
    cp_commit();
    cp_wait_all();
    __syncthreads();

    for (int it = 0; it < 8; it++) {
        const int buf = it & 1;
        if (it < 7) { GCOPY_B((it + 1) * 64, buf ^ 1); cp_commit(); }
#pragma unroll
        for (int ks = 0; ks < 4; ks++) {
            uint32_t af[2][4];
#pragma unroll
            for (int mt = 0; mt < 2; mt++)
                ldmx4(af[mt], uA[buf] +
                      ((warp_m * 32 + mt * 16 + a_row15) * ASTRIDE + ks * 16 + a_k8) * 2);
#pragma unroll
            for (int p = 0; p < 4; p++) {
                uint32_t bf[4];
                ldmx4(bf, uB[buf] +
                      ((warp_n * 64 + p * 16 + b_noff) * ASTRIDE + ks * 16 + b_k8) * 2);
                mma16816(acc[0][2 * p],     af[0], bf[0], bf[1]);
                mma16816(acc[0][2 * p + 1], af[0], bf[2], bf[3]);
                mma16816(acc[1][2 * p],     af[1], bf[0], bf[1]);
                mma16816(acc[1][2 * p + 1], af[1], bf[2], bf[3]);
            }
        }
        if (it < 7) GBUILD_A((it + 1) * 64, buf ^ 1);
        cp_wait_all();
        __syncthreads();
    }

    const int rA = warp_m * 32 + (lane >> 2);
    const int cA = warp_n * 64 + (lane & 3) * 2;
#pragma unroll
    for (int mt = 0; mt < 2; mt++)
#pragma unroll
        for (int hf = 0; hf < 2; hf++) {
            const int row = rA + mt * 16 + hf * 8;
            __half* dst = (__half*)g_Gh + (size_t)(g0 + row) * OUTD;
#pragma unroll
            for (int nt = 0; nt < 8; nt++) {
                const int col = cA + nt * 8;
                *(uint32_t*)(dst + col) = packh2(acc[mt][nt][2 * hf], acc[mt][nt][2 * hf + 1]);
            }
        }
}

__global__ __launch_bounds__(256, 2) void prep_kernel(const float* __restrict__ xyz_hi,
                                                      const float* __restrict__ xyz_lo,
                                                      const float* __restrict__ feat_lo) {
    extern __shared__ char sm[];
    if (blockIdx.x < 128) knn_body(sm, xyz_hi, xyz_lo);
    else                  gemm_g_body(sm, feat_lo);
}

// ---------------------------------------------------------------------------
// Fused kernel: 64x256 tile, 256 threads, 2 CTAs/SM, warp grid 2m x 4n.
// SMEM (dynamic, bytes):
//   WSM 0      : 192 floats                 768
//   ISM 768    : 192 ints                   768
//   A   1536   : 2 x [64][72] half        18432  (H overlays this region)
//   H   1536   : [64][264] half           33792
//   B   35328  : 2 x [256][72] half       73728
//   total 109056
// ---------------------------------------------------------------------------
#define WSM_OFF  0
#define ISM_OFF  768
#define A_OFF    1536
#define A_BYTES  9216
#define H_OFF    1536
#define B_OFF    35328
#define B_BYTES  36864
#define SMEM_TOTAL 109056

__global__ __launch_bounds__(256, 2) void fused_kernel(
        const float* __restrict__ feat_skip,
        const float* __restrict__ b1,
        const float* __restrict__ b2,
        const float* __restrict__ gamma,
        const float* __restrict__ beta,
        float* __restrict__ out) {
    extern __shared__ char sm[];
    const uint32_t sb = smem_u32(sm);

    const int tid    = threadIdx.x;
    const int wid    = tid >> 5;
    const int lane   = tid & 31;
    const int warp_m = wid & 1;
    const int warp_n = wid >> 1;
    const int m0     = blockIdx.x * 64;
    const int bb     = m0 >> 13;

    float* Wsm = (float*)(sm + WSM_OFF);
    int*   Ism = (int*)(sm + ISM_OFF);
    for (int i = tid; i < 192; i += 256) {
        Wsm[i] = g_w[(size_t)m0 * 3 + i];
        Ism[i] = g_idx[(size_t)m0 * 3 + i];
    }

    const uint32_t uA[2] = { sb + A_OFF, sb + A_OFF + A_BYTES };
    const uint32_t uB[2] = { sb + B_OFF, sb + B_OFF + B_BYTES };
    const uint32_t uH    = sb + H_OFF;

    const int a_row15 = lane & 15;
    const int a_k8    = (lane & 16) ? 8 : 0;
    const int b_noff  = (lane & 7) + ((lane & 16) ? 8 : 0);
    const int b_k8    = (lane & 8) ? 8 : 0;
    const int fx = tid & 15, r0 = tid >> 4;

    float acc[2][8][4];
#pragma unroll
    for (int mt = 0; mt < 2; mt++)
#pragma unroll
        for (int nt = 0; nt < 8; nt++)
#pragma unroll
            for (int e = 0; e < 4; e++) acc[mt][nt][e] = 0.0f;

#define BUILD_A(K0, BUF)                                                          \
    do {                                                                          \
        char* Ab = sm + A_OFF + (BUF) * A_BYTES;                                  \
        _Pragma("unroll")                                                         \
        for (int i = 0; i < 4; i++) {                                             \
            const int row = r0 + i * 16;                                          \
            float4 v = *(const float4*)(feat_skip +                               \
                    (size_t)(m0 + row) * SKIPD + (K0) + fx * 4);                  \
            *(uint2*)(Ab + row * (ASTRIDE * 2) + fx * 8) =                        \
                make_uint2(packh2(v.x, v.y), packh2(v.z, v.w));                   \
        }                                                                         \
    } while (0)

#define COPY_B(WP, KDIM, K0, BUF)                                                 \
    do {                                                                          \
        const uint32_t Bb = uB[(BUF)];                                            \
        _Pragma("unroll")                                                         \
        for (int j = 0; j < 8; j++) {                                             \
            const int s = tid + j * 256;                                          \
            const int n = s >> 3, c = s & 7;                                      \
            cpasync16(Bb + n * (ASTRIDE * 2) + c * 16,                            \
                      (const char*)(WP) + ((size_t)n * (KDIM) + (K0)) * 2 + c * 16); \
        }                                                                         \
    } while (0)

#define MMA_CHUNK(ABASE, ASTR, AKOFF, BBUF)                                       \
    do {                                                                          \
        _Pragma("unroll")                                                         \
        for (int ks = 0; ks < 4; ks++) {                                          \
            uint32_t af[2][4];                                                    \
            _Pragma("unroll")                                                     \
            for (int mt = 0; mt < 2; mt++)                                        \
                ldmx4(af[mt], (ABASE) +                                           \
                      ((warp_m * 32 + mt * 16 + a_row15) * (ASTR) +               \
                       (AKOFF) + ks * 16 + a_k8) * 2);                            \
            _Pragma("unroll")                                                     \
            for (int p = 0; p < 4; p++) {                                         \
                uint32_t bf[4];                                                   \
                ldmx4(bf, (BBUF) +                                                \
                      ((warp_n * 64 + p * 16 + b_noff) * ASTRIDE +                \
                       ks * 16 + b_k8) * 2);                                      \
                mma16816(acc[0][2 * p],     af[0], bf[0], bf[1]);                 \
                mma16816(acc[0][2 * p + 1], af[0], bf[2], bf[3]);                 \
                mma16816(acc[1][2 * p],     af[1], bf[0], bf[1]);                 \
                mma16816(acc[1][2 * p + 1], af[1], bf[2], bf[3]);                 \
            }                                                                     \
        }                                                                         \
    } while (0)

    // ======================= GEMM 1: K = 256 (4 chunks) ==================
    BUILD_A(0, 0);
    COPY_B(g_W1h, IND, 0, 0);
    cp_commit();
    cp_wait_all();
    __syncthreads();

    for (int it = 0; it < 4; it++) {
        const int buf = it & 1;
        if (it < 3) { COPY_B(g_W1h, IND, (it + 1) * 64, buf ^ 1); cp_commit(); }
        MMA_CHUNK(uA[buf], ASTRIDE, 0, uB[buf]);
        if (it < 3) BUILD_A((it + 1) * 64, buf ^ 1);
        cp_wait_all();
        __syncthreads();
    }

    // ========= Epilogue 1: acc += b1 + IDW(Gh); relu; -> H fp16 ==========
    {
        const int rA = warp_m * 32 + (lane >> 2);
        const int cA = warp_n * 64 + (lane & 3) * 2;
#pragma unroll
        for (int mt = 0; mt < 2; mt++)
#pragma unroll
            for (int hf = 0; hf < 2; hf++) {
                const int row = rA + mt * 16 + hf * 8;
                const float w0 = Wsm[row * 3 + 0];
                const float w1 = Wsm[row * 3 + 1];
                const float w2 = Wsm[row * 3 + 2];
                const __half* G0 = (const __half*)g_Gh + ((size_t)bb * Sv + Ism[row * 3 + 0]) * OUTD;
                const __half* G1 = (const __half*)g_Gh + ((size_t)bb * Sv + Ism[row * 3 + 1]) * OUTD;
                const __half* G2 = (const __half*)g_Gh + ((size_t)bb * Sv + Ism[row * 3 + 2]) * OUTD;
#pragma unroll
                for (int nt = 0; nt < 8; nt++) {
                    const int col = cA + nt * 8;
                    float2 f0 = __half22float2(*(const __half2*)(G0 + col));
                    float2 f1 = __half22float2(*(const __half2*)(G1 + col));
                    float2 f2 = __half22float2(*(const __half2*)(G2 + col));
                    float v0 = acc[mt][nt][2 * hf]     + b1[col];
                    float v1 = acc[mt][nt][2 * hf + 1] + b1[col + 1];
                    v0 = fmaf(w0, f0.x, fmaf(w1, f1.x, fmaf(w2, f2.x, v0)));
                    v1 = fmaf(w0, f0.y, fmaf(w1, f1.y, fmaf(w2, f2.y, v1)));
                    v0 = fmaxf(v0, 0.0f);
                    v1 = fmaxf(v1, 0.0f);
                    *(uint32_t*)(sm + H_OFF + (row * HSTRIDE + col) * 2) = packh2(v0, v1);
                }
            }
    }
    __syncthreads();

    // ======================= GEMM 2: K = 256 (4 chunks) ==================
#pragma unroll
    for (int mt = 0; mt < 2; mt++)
#pragma unroll
        for (int nt = 0; nt < 8; nt++)
#pragma unroll
            for (int e = 0; e < 4; e++) acc[mt][nt][e] = 0.0f;

    COPY_B(g_W2h, OUTD, 0, 0);
    cp_commit();
    cp_wait_all();
    __syncthreads();

    for (int it = 0; it < 4; it++) {
        const int buf = it & 1;
        if (it < 3) { COPY_B(g_W2h, OUTD, (it + 1) * 64, buf ^ 1); cp_commit(); }
        MMA_CHUNK(uH, HSTRIDE, it * 64, uB[buf]);
        cp_wait_all();
        __syncthreads();
    }

    // ======================= Epilogue 2: LayerNorm -> out ================
    {
        float* Red  = (float*)(sm + B_OFF);   // [64][4]
        float* Red2 = Red + 256;              // [64][4]
        float* Mu   = Red2 + 256;             // [64]
        float* Rs   = Mu + 64;                // [64]

        const int rA = warp_m * 32 + (lane >> 2);
        const int cA = warp_n * 64 + (lane & 3) * 2;

#pragma unroll
        for (int mt = 0; mt < 2; mt++)
#pragma unroll
            for (int hf = 0; hf < 2; hf++) {
                const int row = rA + mt * 16 + hf * 8;
                float s = 0.0f, sq = 0.0f;
#pragma unroll
                for (int nt = 0; nt < 8; nt++) {
                    const int col = cA + nt * 8;
                    float v0 = acc[mt][nt][2 * hf]     + b2[col];
                    float v1 = acc[mt][nt][2 * hf + 1] + b2[col + 1];
                    s += v0 + v1;
                    sq = fmaf(v0, v0, fmaf(v1, v1, sq));
                }
                s  += __shfl_xor_sync(0xffffffffu, s, 1);
                s  += __shfl_xor_sync(0xffffffffu, s, 2);
                sq += __shfl_xor_sync(0xffffffffu, sq, 1);
                sq += __shfl_xor_sync(0xffffffffu, sq, 2);
                if ((lane & 3) == 0) {
                    Red[row * 4 + warp_n]  = s;
                    Red2[row * 4 + warp_n] = sq;
                }
            }
        __syncthreads();
        if (tid < 64) {
            float s  = Red[tid * 4]  + Red[tid * 4 + 1]  + Red[tid * 4 + 2]  + Red[tid * 4 + 3];
            float sq = Red2[tid * 4] + Red2[tid * 4 + 1] + Red2[tid * 4 + 2] + Red2[tid * 4 + 3];
            const float mu  = s * (1.0f / 256.0f);
            const float var = fmaxf(sq * (1.0f / 256.0f) - mu * mu, 0.0f);
            Mu[tid] = mu;
            Rs[tid] = rsqrtf(var + 1e-5f);
        }
        __syncthreads();

#pragma unroll
        for (int mt = 0; mt < 2; mt++)
#pragma unroll
            for (int hf = 0; hf < 2; hf++) {
                const int row  = rA + mt * 16 + hf * 8;
                const float mu = Mu[row], rstd = Rs[row];
                float* dst = out + (size_t)(m0 + row) * OUTD;
#pragma unroll
                for (int nt = 0; nt < 8; nt++) {
                    const int col = cA + nt * 8;
                    float v0 = acc[mt][nt][2 * hf]     + b2[col];
                    float v1 = acc[mt][nt][2 * hf + 1] + b2[col + 1];
                    float2 o;
                    o.x = fmaf((v0 - mu) * rstd, gamma[col],     beta[col]);
                    o.y = fmaf((v1 - mu) * rstd, gamma[col + 1], beta[col + 1]);
                    *(float2*)(dst + col) = o;
                }
            }
    }
}

// ---------------------------------------------------------------------------
extern "C" void kernel_launch(void* const* d_in, const int* in_sizes, int n_in,
                              void* d_out, int out_size) {
    const float* xyz_hi    = (const float*)d_in[0];
    const float* xyz_lo    = (const float*)d_in[1];
    const float* feat_skip = (const float*)d_in[2];
    const float* feat_lo   = (const float*)d_in[3];
    const float* W1        = (const float*)d_in[4];
    const float* b1        = (const float*)d_in[5];
    const float* W2        = (const float*)d_in[6];
    const float* b2        = (const float*)d_in[7];
    const float* gamma     = (const float*)d_in[8];
    const float* beta      = (const float*)d_in[9];
    float* out = (float*)d_out;

    __half* w1h; cudaGetSymbolAddress((void**)&w1h, g_W1h);
    __half* w2h; cudaGetSymbolAddress((void**)&w2h, g_W2h);

    transpose_both<<<dim3(8, 32), dim3(32, 8)>>>(W1, W2, w1h, w2h);

    cudaFuncSetAttribute(prep_kernel,
                         cudaFuncAttributeMaxDynamicSharedMemorySize, GSMEM);
    prep_kernel<<<256, 256, GSMEM>>>(xyz_hi, xyz_lo, feat_lo);

    cudaFuncSetAttribute(fused_kernel,
                         cudaFuncAttributeMaxDynamicSharedMemorySize, SMEM_TOTAL);
    fused_kernel<<<(Bv * Nv) / 64, 256, SMEM_TOTAL>>>(
        feat_skip, b1, b2, gamma, beta, out);
}